// round 5
// baseline (speedup 1.0000x reference)
#include <cuda_runtime.h>
#include <cuda_bf16.h>
#include <cstdint>

// Fused gamma-pdf-weighted MSE mean reduction — TMA-streamed single kernel.
// mean( 0.5*(output-target)^2 * ef(target) )
// ef(y) = (BETA - c)*(1 - pdf(y)/FX_MAX) + c,  c = 1/(Y_MAX - Y_MIN)
// pdf/FX_MAX < 4e-19 for all fp32 uniform targets except exact zeros ->
// log/exp only in a cold branch (y < 1e-6); hot loop has no MUFU.
//
// R5: LDG path plateaued at ~5TB/s (DRAM 61-64%) regardless of per-thread
// MLP. Stream via cp.async.bulk (TMA engine) into a 2-stage SMEM ring,
// compute from SMEM. 4 blocks/SM x 2 stages x 16KB = deep HW-queued traffic.

#define NBLK    592          // 148 SMs * 4
#define NTH     256
#define TILE    2048         // floats per stream per stage (8 KB)
#define TILE_B  (TILE * 4)   // 8192 bytes
#define NSTG    2

__device__ float        g_part[NBLK];
__device__ unsigned int g_count;     // zero-init; self-resetting via atomicInc wrap

// ---------------- math ----------------
__device__ __forceinline__ float elem_val(float o, float y) {
    const float A1        = -0.9355570857535674f;            // EST_A - 1
    const float NEG_LOC   = 1.1328205299926424e-27f;         // -EST_LOC
    const float INV_SCALE = (float)(1.0 / 1.5376362609160314);
    const float C0        = -58.4492351f;                    // -lgamma(a)-ln(scale)-ln(FX_MAX)
    const float C         = (float)(1.0 / 107.2185);
    const float BC        = 5.0f - (float)(1.0 / 107.2185);

    float r = 0.0f;
    if (y < 1e-6f) {                       // cold path
        float x  = (y + NEG_LOC) * INV_SCALE;
        float lp = fmaf(A1, __logf(x), C0) - x;
        r = __expf(lp);
    }
    float ef   = fmaf(BC, 1.0f - r, C);
    float diff = o - y;
    return 0.5f * diff * diff * ef;
}

__device__ __forceinline__ float quad_val(float4 o, float4 t) {
    return elem_val(o.x, t.x) + elem_val(o.y, t.y)
         + elem_val(o.z, t.z) + elem_val(o.w, t.w);
}

// ---------------- PTX helpers ----------------
__device__ __forceinline__ uint32_t smem_u32(const void* p) {
    uint32_t a;
    asm("{ .reg .u64 t; cvta.to.shared.u64 t, %1; cvt.u32.u64 %0, t; }"
        : "=r"(a) : "l"(p));
    return a;
}
__device__ __forceinline__ void mbar_init(uint32_t mbar, uint32_t count) {
    asm volatile("mbarrier.init.shared.b64 [%0], %1;"
                 :: "r"(mbar), "r"(count) : "memory");
}
__device__ __forceinline__ void mbar_expect_tx(uint32_t mbar, uint32_t bytes) {
    asm volatile("mbarrier.arrive.expect_tx.shared.b64 _, [%0], %1;"
                 :: "r"(mbar), "r"(bytes) : "memory");
}
__device__ __forceinline__ void mbar_wait(uint32_t mbar, uint32_t parity) {
    uint32_t done;
    do {
        asm volatile(
            "{ .reg .pred p;\n"
            "  mbarrier.try_wait.parity.shared.b64 p, [%1], %2;\n"
            "  selp.b32 %0, 1, 0, p; }"
            : "=r"(done) : "r"(mbar), "r"(parity) : "memory");
    } while (!done);
}
__device__ __forceinline__ void bulk_ld(uint32_t dst, const void* src,
                                        uint32_t bytes, uint32_t mbar) {
    asm volatile(
        "cp.async.bulk.shared::cluster.global.mbarrier::complete_tx::bytes "
        "[%0], [%1], %2, [%3];"
        :: "r"(dst), "l"(src), "r"(bytes), "r"(mbar) : "memory");
}
__device__ __forceinline__ void fence_proxy_async_shared() {
    asm volatile("fence.proxy.async.shared::cta;" ::: "memory");
}

// ---------------- kernel ----------------
__global__ __launch_bounds__(NTH) void loss_tma_kernel(
    const float* __restrict__ out, const float* __restrict__ tgt,
    float* __restrict__ result, int n)
{
    __shared__ alignas(16) float   s_o[NSTG][TILE];
    __shared__ alignas(16) float   s_t[NSTG][TILE];
    __shared__ alignas(8) uint64_t s_mbar[NSTG];
    __shared__ bool                s_last;

    const int tid  = threadIdx.x;
    const int lane = tid & 31;
    const int warp = tid >> 5;
    const int bid  = blockIdx.x;
    const int G    = gridDim.x;

    const int ntiles = n / TILE;
    // tiles for this block: bid, bid+G, bid+2G, ...
    const int count = (bid < ntiles) ? (ntiles - bid + G - 1) / G : 0;

    uint32_t mb[NSTG];
    mb[0] = smem_u32(&s_mbar[0]);
    mb[1] = smem_u32(&s_mbar[1]);

    if (tid == 0) {
        mbar_init(mb[0], 1);
        mbar_init(mb[1], 1);
        fence_proxy_async_shared();
    }
    __syncthreads();

    // prologue: fill both stages
    if (tid == 0) {
        for (int p = 0; p < NSTG && p < count; ++p) {
            long long tk = (long long)(bid) + (long long)p * G;
            const float* po = out + tk * TILE;
            const float* pt = tgt + tk * TILE;
            mbar_expect_tx(mb[p], 2 * TILE_B);
            bulk_ld(smem_u32(&s_o[p][0]), po, TILE_B, mb[p]);
            bulk_ld(smem_u32(&s_t[p][0]), pt, TILE_B, mb[p]);
        }
    }

    float sum = 0.0f;
    for (int k = 0; k < count; ++k) {
        const int s  = k & 1;
        const int ph = (k >> 1) & 1;
        mbar_wait(mb[s], ph);

        const float4* so = (const float4*)&s_o[s][0];
        const float4* st = (const float4*)&s_t[s][0];
        #pragma unroll
        for (int j = 0; j < TILE / 4 / NTH; ++j) {   // 2 float4 per thread
            int idx = tid + j * NTH;
            sum += quad_val(so[idx], st[idx]);
        }
        __syncthreads();                   // all threads done reading stage s

        if (tid == 0 && k + NSTG < count) {
            long long tk = (long long)(bid) + (long long)(k + NSTG) * G;
            const float* po = out + tk * TILE;
            const float* pt = tgt + tk * TILE;
            mbar_expect_tx(mb[s], 2 * TILE_B);
            bulk_ld(smem_u32(&s_o[s][0]), po, TILE_B, mb[s]);
            bulk_ld(smem_u32(&s_t[s][0]), pt, TILE_B, mb[s]);
        }
    }

    // scalar tail (n % TILE)
    for (int i = ntiles * TILE + bid * NTH + tid; i < n; i += G * NTH)
        sum += elem_val(out[i], tgt[i]);

    // ---- block reduce (full-warp shuffles only) ----
    #pragma unroll
    for (int off = 16; off > 0; off >>= 1)
        sum += __shfl_down_sync(0xFFFFFFFFu, sum, off);

    __shared__ float s_warp[NTH / 32];
    if (lane == 0) s_warp[warp] = sum;
    __syncthreads();

    if (warp == 0) {
        float v = (lane < NTH / 32) ? s_warp[lane] : 0.0f;
        #pragma unroll
        for (int off = 16; off > 0; off >>= 1)
            v += __shfl_down_sync(0xFFFFFFFFu, v, off);
        if (lane == 0) {
            g_part[bid] = v;
            __threadfence();                                   // release
            unsigned int prev = atomicInc(&g_count, NBLK - 1u); // wraps -> 0
            s_last = (prev == NBLK - 1u);
        }
    }
    __syncthreads();

    if (s_last) {
        __threadfence();                   // acquire before reading g_part
        double acc = 0.0;                  // fixed-order deterministic
        for (int i = tid; i < NBLK; i += NTH)
            acc += (double)g_part[i];

        #pragma unroll
        for (int off = 16; off > 0; off >>= 1)
            acc += __shfl_down_sync(0xFFFFFFFFu, acc, off);

        __shared__ double s_d[NTH / 32];
        if (lane == 0) s_d[warp] = acc;
        __syncthreads();

        if (warp == 0) {
            double v = (lane < NTH / 32) ? s_d[lane] : 0.0;
            #pragma unroll
            for (int off = 16; off > 0; off >>= 1)
                v += __shfl_down_sync(0xFFFFFFFFu, v, off);
            if (lane == 0)
                result[0] = (float)(v / (double)n);
        }
    }
}

extern "C" void kernel_launch(void* const* d_in, const int* in_sizes, int n_in,
                              void* d_out, int out_size)
{
    const float* output = (const float*)d_in[0];
    const float* target = (const float*)d_in[1];
    const int n = in_sizes[0];

    loss_tma_kernel<<<NBLK, NTH>>>(output, target, (float*)d_out, n);
}

// round 6
// speedup vs baseline: 1.0239x; 1.0239x over previous
#include <cuda_runtime.h>
#include <cuda_bf16.h>
#include <cstdint>

// Fused gamma-pdf-weighted MSE mean reduction — single kernel, last-block-done,
// Blackwell 256-bit loads (ld.global.nc.v8.f32 -> LDG.E.256).
//
// mean( 0.5*(output-target)^2 * ef(target) )
// ef(y) = (BETA - c)*(1 - pdf(y)/FX_MAX) + c,  c = 1/(Y_MAX - Y_MIN)
// pdf/FX_MAX < 4e-19 for fp32 uniform targets except exact zeros ->
// log/exp only in a cold branch (y < 1e-6); hot loop has no MUFU.
//
// R6 rationale: R3/R4/R5 all plateau at 5.0+-0.3 TB/s with DRAM ~36% idle,
// independent of bytes-in-flight (120..300+ loads/SM). Suspect: per-SM
// outstanding-request tracking saturates per-instruction. LDG.E.256 halves
// instruction count per byte at identical footprint.

#define NBLK 740    // 148 SMs * 5
#define NTH  256

__device__ float        g_part[NBLK];
__device__ unsigned int g_count;   // zero-init; self-resetting via atomicInc wrap

__device__ __forceinline__ float elem_val(float o, float y) {
    const float A1        = -0.9355570857535674f;            // EST_A - 1
    const float NEG_LOC   = 1.1328205299926424e-27f;         // -EST_LOC
    const float INV_SCALE = (float)(1.0 / 1.5376362609160314);
    const float C0        = -58.4492351f;                    // -lgamma(a)-ln(scale)-ln(FX_MAX)
    const float C         = (float)(1.0 / 107.2185);
    const float BC        = 5.0f - (float)(1.0 / 107.2185);

    float r = 0.0f;
    if (y < 1e-6f) {                      // cold path: only (near-)zero targets
        float x  = (y + NEG_LOC) * INV_SCALE;
        float lp = fmaf(A1, __logf(x), C0) - x;
        r = __expf(lp);
    }
    float ef   = fmaf(BC, 1.0f - r, C);
    float diff = o - y;
    return 0.5f * diff * diff * ef;
}

// 256-bit read-only global load (sm_100+): one LDG.E.256 per call.
__device__ __forceinline__ void ldg256(const float* __restrict__ p, float r[8]) {
    asm volatile("ld.global.nc.v8.f32 {%0,%1,%2,%3,%4,%5,%6,%7}, [%8];"
                 : "=f"(r[0]), "=f"(r[1]), "=f"(r[2]), "=f"(r[3]),
                   "=f"(r[4]), "=f"(r[5]), "=f"(r[6]), "=f"(r[7])
                 : "l"(p));
}

__device__ __forceinline__ float oct_val(const float o[8], const float t[8]) {
    float s = 0.0f;
    #pragma unroll
    for (int j = 0; j < 8; ++j) s += elem_val(o[j], t[j]);
    return s;
}

__global__ __launch_bounds__(NTH, 5) void loss_fused_kernel(
    const float* __restrict__ out, const float* __restrict__ tgt,
    float* __restrict__ result, int n)
{
    const int tid    = threadIdx.x;
    const int lane   = tid & 31;
    const int warp   = tid >> 5;
    const int idx    = blockIdx.x * NTH + tid;
    const int stride = gridDim.x * NTH;
    const int n8     = n >> 3;            // v8 chunks

    float sum = 0.0f;
    int i = idx;

    // Unroll-by-2: 4 x LDG.E.256 issued before compute (128B in flight/thread).
    for (; i + stride < n8; i += 2 * stride) {
        float o0[8], t0[8], o1[8], t1[8];
        ldg256(out + (size_t)i * 8,            o0);
        ldg256(tgt + (size_t)i * 8,            t0);
        ldg256(out + (size_t)(i + stride) * 8, o1);
        ldg256(tgt + (size_t)(i + stride) * 8, t1);
        sum += oct_val(o0, t0);
        sum += oct_val(o1, t1);
    }
    for (; i < n8; i += stride) {          // v8 remainder
        float o0[8], t0[8];
        ldg256(out + (size_t)i * 8, o0);
        ldg256(tgt + (size_t)i * 8, t0);
        sum += oct_val(o0, t0);
    }
    for (int j = (n8 << 3) + idx; j < n; j += stride)   // scalar tail
        sum += elem_val(out[j], tgt[j]);

    // ---- block reduce (full-warp shuffles only) ----
    #pragma unroll
    for (int off = 16; off > 0; off >>= 1)
        sum += __shfl_down_sync(0xFFFFFFFFu, sum, off);

    __shared__ float s_warp[NTH / 32];
    __shared__ bool  s_last;
    if (lane == 0) s_warp[warp] = sum;
    __syncthreads();

    if (warp == 0) {                      // full warp active
        float v = (lane < NTH / 32) ? s_warp[lane] : 0.0f;
        #pragma unroll
        for (int off = 16; off > 0; off >>= 1)
            v += __shfl_down_sync(0xFFFFFFFFu, v, off);
        if (lane == 0) {
            g_part[blockIdx.x] = v;
            __threadfence();                                   // release
            unsigned int prev = atomicInc(&g_count, NBLK - 1u); // wraps -> 0
            s_last = (prev == NBLK - 1u);
        }
    }
    __syncthreads();

    if (s_last) {
        __threadfence();                  // acquire before reading g_part
        double acc = 0.0;                 // fixed-order deterministic reduce
        for (int k = tid; k < NBLK; k += NTH)
            acc += (double)g_part[k];

        #pragma unroll
        for (int off = 16; off > 0; off >>= 1)
            acc += __shfl_down_sync(0xFFFFFFFFu, acc, off);

        __shared__ double s_d[NTH / 32];
        if (lane == 0) s_d[warp] = acc;
        __syncthreads();

        if (warp == 0) {                  // full warp active
            double v = (lane < NTH / 32) ? s_d[lane] : 0.0;
            #pragma unroll
            for (int off = 16; off > 0; off >>= 1)
                v += __shfl_down_sync(0xFFFFFFFFu, v, off);
            if (lane == 0)
                result[0] = (float)(v / (double)n);
        }
    }
}

extern "C" void kernel_launch(void* const* d_in, const int* in_sizes, int n_in,
                              void* d_out, int out_size)
{
    const float* output = (const float*)d_in[0];
    const float* target = (const float*)d_in[1];
    const int n = in_sizes[0];

    loss_fused_kernel<<<NBLK, NTH>>>(output, target, (float*)d_out, n);
}